// round 1
// baseline (speedup 1.0000x reference)
#include <cuda_runtime.h>
#include <cstring>

// Problem shape
#define T_ROWS   65536      // 64*128*8
#define D_DIM    256
#define P_PROTOS 512

// GEMM tile config
#define BM 128
#define BN 128
#define BK 16

// Scratch (device globals: no allocation allowed)
__device__ int   g_idx[T_ROWS];
__device__ float g_pnorm[P_PROTOS];

struct VI { float v; int i; };

// ---------------------------------------------------------------------------
// K0: prototype squared norms + zero the loss slot in d_out
// ---------------------------------------------------------------------------
__global__ void k_pnorm(const float* __restrict__ protos, float* __restrict__ loss)
{
    int p = blockIdx.x;           // one block per prototype
    int t = threadIdx.x;          // 64 threads
    float4 v = ((const float4*)(protos + (size_t)p * D_DIM))[t];
    float s = v.x * v.x + v.y * v.y + v.z * v.z + v.w * v.w;
    #pragma unroll
    for (int o = 16; o; o >>= 1) s += __shfl_down_sync(0xffffffffu, s, o);
    __shared__ float ws[2];
    if ((t & 31) == 0) ws[t >> 5] = s;
    __syncthreads();
    if (t == 0) g_pnorm[p] = ws[0] + ws[1];
    if (p == 0 && t == 0) *loss = 0.0f;   // d_out is poisoned; must init
}

// ---------------------------------------------------------------------------
// K1: fused GEMM + argmin.  dist_j = ||p_j||^2 - 2 <x_t, p_j>  (||x||^2 const)
// Packed fp32x2 FMA: accumulate pairs of prototypes per 64-bit register.
// ---------------------------------------------------------------------------
__global__ void __launch_bounds__(256)
k_argmin(const float* __restrict__ x, const float* __restrict__ protos)
{
    // A stored duplicated: As[k][r] = (a, a)  -> LDS.128 yields two dup-pairs
    __shared__ float2 As[BK][BM];            // 16 KB
    __shared__ float  Bs[BK][BN];            // 8 KB
    __shared__ VI     Red[BM][16];           // 16 KB, used only at the end

    const int tid = threadIdx.x;
    const int tx  = tid & 15;     // prototype-column group (8 protos)
    const int ty  = tid >> 4;     // row group (8 rows)
    const int row0 = blockIdx.x * BM;

    float bestv[8];
    int   besti[8];
    #pragma unroll
    for (int i = 0; i < 8; i++) { bestv[i] = 3.4e38f; besti[i] = 0; }

    for (int nc = 0; nc < P_PROTOS / BN; ++nc) {            // 4 proto chunks
        const int p0 = nc * BN;
        unsigned long long acc[8][4];
        #pragma unroll
        for (int r = 0; r < 8; r++)
            #pragma unroll
            for (int c = 0; c < 4; c++) acc[r][c] = 0ull;   // (0.f,0.f)

        for (int kc = 0; kc < D_DIM / BK; ++kc) {           // 16 K chunks
            __syncthreads();
            // stage A (rows) and B (protos): 512 float4 each, 2 per thread
            #pragma unroll
            for (int i = 0; i < 2; i++) {
                int f  = tid + i * 256;
                int r  = f >> 2;
                int kq = f & 3;
                float4 va = __ldg((const float4*)(x + (size_t)(row0 + r) * D_DIM + kc * BK + kq * 4));
                As[kq * 4 + 0][r] = make_float2(va.x, va.x);
                As[kq * 4 + 1][r] = make_float2(va.y, va.y);
                As[kq * 4 + 2][r] = make_float2(va.z, va.z);
                As[kq * 4 + 3][r] = make_float2(va.w, va.w);
                float4 vb = __ldg((const float4*)(protos + (size_t)(p0 + r) * D_DIM + kc * BK + kq * 4));
                Bs[kq * 4 + 0][r] = vb.x;
                Bs[kq * 4 + 1][r] = vb.y;
                Bs[kq * 4 + 2][r] = vb.z;
                Bs[kq * 4 + 3][r] = vb.w;
            }
            __syncthreads();

            #pragma unroll
            for (int k = 0; k < BK; ++k) {
                unsigned long long ap[8], bp[4];
                const ulonglong2* aptr = (const ulonglong2*)(&As[k][ty * 8]);
                #pragma unroll
                for (int i = 0; i < 4; i++) {
                    ulonglong2 u = aptr[i];
                    ap[2 * i]     = u.x;      // (a_r, a_r)
                    ap[2 * i + 1] = u.y;      // (a_{r+1}, a_{r+1})
                }
                const ulonglong2* bptr = (const ulonglong2*)(&Bs[k][tx * 8]);
                {
                    ulonglong2 u0 = bptr[0];
                    ulonglong2 u1 = bptr[1];
                    bp[0] = u0.x; bp[1] = u0.y; bp[2] = u1.x; bp[3] = u1.y;
                }
                #pragma unroll
                for (int r = 0; r < 8; r++)
                    #pragma unroll
                    for (int c = 0; c < 4; c++)
                        asm("fma.rn.f32x2 %0, %1, %2, %0;"
                            : "+l"(acc[r][c]) : "l"(ap[r]), "l"(bp[c]));
            }
        }

        // epilogue for this prototype chunk: dist = pnorm - 2*dot, track min
        #pragma unroll
        for (int r = 0; r < 8; r++) {
            #pragma unroll
            for (int c = 0; c < 4; c++) {
                float2 f;
                memcpy(&f, &acc[r][c], 8);
                int pa = p0 + tx * 8 + 2 * c;
                float da = g_pnorm[pa]     - 2.0f * f.x;
                float db = g_pnorm[pa + 1] - 2.0f * f.y;
                if (da < bestv[r]) { bestv[r] = da; besti[r] = pa; }
                if (db < bestv[r]) { bestv[r] = db; besti[r] = pa + 1; }
            }
        }
    }

    // reduce argmin across the 16 tx groups per row
    __syncthreads();
    #pragma unroll
    for (int r = 0; r < 8; r++) {
        Red[ty * 8 + r][tx].v = bestv[r];
        Red[ty * 8 + r][tx].i = besti[r];
    }
    __syncthreads();
    if (tid < BM) {
        float v = Red[tid][0].v;
        int   b = Red[tid][0].i;
        #pragma unroll
        for (int j = 1; j < 16; j++) {
            VI e = Red[tid][j];
            if (e.v < v || (e.v == v && e.i < b)) { v = e.v; b = e.i; }
        }
        g_idx[row0 + tid] = b;
    }
}

// ---------------------------------------------------------------------------
// K2: gather prototypes, write proto + residuals, accumulate loss
// loss = 1.25 * mean((x - p)^2);  proto == proto_raw (straight-through)
// ---------------------------------------------------------------------------
__global__ void __launch_bounds__(256)
k_output(const float* __restrict__ x, const float* __restrict__ protos,
         float* __restrict__ out_proto, float* __restrict__ out_res,
         float* __restrict__ loss)
{
    int g   = blockIdx.x * blockDim.x + threadIdx.x;   // float4 index
    int row = g >> 6;                                  // 64 float4 per row
    int d4  = g & 63;
    int idx = g_idx[row];

    float4 xv = ((const float4*)x)[g];
    float4 pv = __ldg((const float4*)(protos + (size_t)idx * D_DIM) + d4);
    float4 rv = make_float4(xv.x - pv.x, xv.y - pv.y, xv.z - pv.z, xv.w - pv.w);

    ((float4*)out_proto)[g] = pv;
    ((float4*)out_res)[g]   = rv;

    float s = rv.x * rv.x + rv.y * rv.y + rv.z * rv.z + rv.w * rv.w;
    #pragma unroll
    for (int o = 16; o; o >>= 1) s += __shfl_down_sync(0xffffffffu, s, o);
    __shared__ float ws[8];
    if ((threadIdx.x & 31) == 0) ws[threadIdx.x >> 5] = s;
    __syncthreads();
    if (threadIdx.x == 0) {
        float t = 0.0f;
        #pragma unroll
        for (int i = 0; i < 8; i++) t += ws[i];
        // scale = 1.25 / (65536*256) = 1.25 * 2^-24
        atomicAdd(loss, t * 7.450580596923828e-08f);
    }
}

// ---------------------------------------------------------------------------
// launch: d_in[0] = x (64,128,8,256) f32, d_in[1] = prototypes (512,256) f32
// d_out: [proto (T*D) | residuals (T*D) | loss (1)]
// ---------------------------------------------------------------------------
extern "C" void kernel_launch(void* const* d_in, const int* in_sizes, int n_in,
                              void* d_out, int out_size)
{
    const float* x      = (const float*)d_in[0];
    const float* protos = (const float*)d_in[1];
    float* out       = (float*)d_out;
    float* out_proto = out;
    float* out_res   = out + (size_t)T_ROWS * D_DIM;
    float* loss      = out + 2ull * (size_t)T_ROWS * D_DIM;

    k_pnorm <<<P_PROTOS, 64>>>(protos, loss);
    k_argmin<<<T_ROWS / BM, 256>>>(x, protos);
    k_output<<<(T_ROWS * (D_DIM / 4)) / 256, 256>>>(x, protos, out_proto, out_res, loss);
}

// round 3
// speedup vs baseline: 2.6038x; 2.6038x over previous
#include <cuda_runtime.h>
#include <cuda_bf16.h>
#include <cstdint>

#define T_ROWS   65536      // 64*128*8
#define D_DIM    256
#define P_PROTOS 512
#define BM       64         // rows per screening CTA
#define MARGIN   3.0f       // bf16 screening error bound is ~1.3 worst-case

// ---- device scratch (no allocations allowed) ----
__device__ __align__(16) __nv_bfloat16 g_pbf[P_PROTOS * D_DIM];
__device__ float g_pnorm[P_PROTOS];
__device__ int   g_cand[T_ROWS * 8];
__device__ int   g_cnt[T_ROWS];

// ---------------------------------------------------------------------------
// mma / ldmatrix primitives (legacy warp-level tensor core path, sm_80+ ISA)
// ---------------------------------------------------------------------------
__device__ __forceinline__ void ldmA(uint32_t* r, uint32_t addr) {
    asm volatile("ldmatrix.sync.aligned.m8n8.x4.shared.b16 {%0,%1,%2,%3}, [%4];"
        : "=r"(r[0]), "=r"(r[1]), "=r"(r[2]), "=r"(r[3]) : "r"(addr));
}
__device__ __forceinline__ void ldmB(uint32_t* r, uint32_t addr) {
    asm volatile("ldmatrix.sync.aligned.m8n8.x2.shared.b16 {%0,%1}, [%2];"
        : "=r"(r[0]), "=r"(r[1]) : "r"(addr));
}
__device__ __forceinline__ void mma16816(float* c, const uint32_t* a, const uint32_t* b) {
    asm volatile("mma.sync.aligned.m16n8k16.row.col.f32.bf16.bf16.f32 "
        "{%0,%1,%2,%3}, {%4,%5,%6,%7}, {%8,%9}, {%0,%1,%2,%3};"
        : "+f"(c[0]), "+f"(c[1]), "+f"(c[2]), "+f"(c[3])
        : "r"(a[0]), "r"(a[1]), "r"(a[2]), "r"(a[3]), "r"(b[0]), "r"(b[1]));
}

// ---------------------------------------------------------------------------
// K0: prototype norms (fp32) + bf16 copy of prototypes + zero loss slot
// ---------------------------------------------------------------------------
__global__ void k_prep(const float* __restrict__ protos, float* __restrict__ loss)
{
    int p = blockIdx.x;           // one block per prototype
    int t = threadIdx.x;          // 64 threads
    float4 v = ((const float4*)(protos + (size_t)p * D_DIM))[t];
    __nv_bfloat162 b0 = __floats2bfloat162_rn(v.x, v.y);
    __nv_bfloat162 b1 = __floats2bfloat162_rn(v.z, v.w);
    *(uint2*)(&g_pbf[(size_t)p * D_DIM + t * 4]) =
        make_uint2(*(uint32_t*)&b0, *(uint32_t*)&b1);

    float s = v.x * v.x + v.y * v.y + v.z * v.z + v.w * v.w;
    #pragma unroll
    for (int o = 16; o; o >>= 1) s += __shfl_down_sync(0xffffffffu, s, o);
    __shared__ float ws[2];
    if ((t & 31) == 0) ws[t >> 5] = s;
    __syncthreads();
    if (t == 0) g_pnorm[p] = ws[0] + ws[1];
    if (p == 0 && t == 0) *loss = 0.0f;
}

// ---------------------------------------------------------------------------
// K1: bf16 tensor-core screening GEMM + per-row min + candidate shortlist.
// dist_j = ||p_j||^2 - 2<x,p_j>   (||x||^2 is row-constant, dropped)
//
// 512 threads = 16 warps: warp grid 2(m: 32 rows) x 8(n: 8 protos).
// Full N=512 dist matrix in smem (stride 513 for conflict-free scan).
// B staged per 64-proto chunk; A staged once (bf16, stride 264 pad).
// ---------------------------------------------------------------------------
#define SM_DIST  0
#define SM_AS    (64 * 513 * 4)                 // 131328
#define SM_BS    (SM_AS + 64 * 264 * 2)         // +33792
#define SM_PN    (SM_BS + 64 * 264 * 2)         // +33792
#define SM_CNT   (SM_PN + 512 * 4)
#define SM_TOTAL (SM_CNT + 64 * 4)              // 201472

__global__ void __launch_bounds__(512, 1)
k_screen(const float* __restrict__ x)
{
    extern __shared__ char sm[];
    float*          distS = (float*)(sm + SM_DIST);
    __nv_bfloat16*  As    = (__nv_bfloat16*)(sm + SM_AS);
    __nv_bfloat16*  Bs    = (__nv_bfloat16*)(sm + SM_BS);
    float*          pnS   = (float*)(sm + SM_PN);
    int*            cntS  = (int*)(sm + SM_CNT);

    const int tid  = threadIdx.x;
    const int row0 = blockIdx.x * BM;

    // stage A: 64 rows x 256 fp32 -> bf16 smem (padded stride 264)
    #pragma unroll
    for (int i = 0; i < 8; i++) {
        int j = tid + i * 512;                 // 0..4095
        int r = j >> 6, c = j & 63;            // 64 float4 per row
        float4 v = __ldg((const float4*)(x + (size_t)(row0 + r) * D_DIM + c * 4));
        __nv_bfloat162 b0 = __floats2bfloat162_rn(v.x, v.y);
        __nv_bfloat162 b1 = __floats2bfloat162_rn(v.z, v.w);
        *(uint2*)(As + r * 264 + c * 4) = make_uint2(*(uint32_t*)&b0, *(uint32_t*)&b1);
    }
    pnS[tid] = g_pnorm[tid];
    if (tid < 64) cntS[tid] = 0;

    const int wid = tid >> 5, lane = tid & 31;
    const int wm = wid & 1;          // 0/1 -> rows [0,32) / [32,64)
    const int wn = wid >> 1;         // 0..7 -> proto cols wn*8 within chunk
    uint32_t asBase = (uint32_t)__cvta_generic_to_shared(As);
    uint32_t bsBase = (uint32_t)__cvta_generic_to_shared(Bs);
    uint32_t aAddr0 = asBase + (uint32_t)(((wm * 32 + (lane & 15)) * 264 + (lane >> 4) * 8) * 2);
    uint32_t aAddr1 = aAddr0 + 16 * 264 * 2;
    uint32_t bAddr  = bsBase + (uint32_t)(((wn * 8 + (lane & 7)) * 264 + ((lane >> 3) & 1) * 8) * 2);

    for (int ch = 0; ch < 8; ch++) {
        __syncthreads();             // previous chunk's mma done before Bs overwrite
        #pragma unroll
        for (int i = 0; i < 4; i++) {
            int j = tid + i * 512;                  // 0..2047
            int r = j >> 5, c = j & 31;             // 64 protos x 32 uint4
            uint4 v = __ldg((const uint4*)(g_pbf + (size_t)(ch * 64 + r) * D_DIM + c * 8));
            *(uint4*)(Bs + r * 264 + c * 8) = v;
        }
        __syncthreads();

        float acc[2][4];
        #pragma unroll
        for (int mt = 0; mt < 2; mt++)
            #pragma unroll
            for (int q = 0; q < 4; q++) acc[mt][q] = 0.f;

        #pragma unroll 4
        for (int k0 = 0; k0 < D_DIM; k0 += 16) {
            uint32_t a0[4], a1[4], b[2];
            ldmA(a0, aAddr0 + k0 * 2);
            ldmA(a1, aAddr1 + k0 * 2);
            ldmB(b,  bAddr  + k0 * 2);
            mma16816(acc[0], a0, b);
            mma16816(acc[1], a1, b);
        }

        // epilogue: dist = pnorm - 2*score into distS
        int g = lane >> 2, t4 = lane & 3;
        int colg = ch * 64 + wn * 8 + 2 * t4;
        float pn0 = pnS[colg], pn1 = pnS[colg + 1];
        #pragma unroll
        for (int mt = 0; mt < 2; mt++) {
            int r = wm * 32 + mt * 16 + g;
            distS[r * 513 + colg]           = pn0 - 2.f * acc[mt][0];
            distS[r * 513 + colg + 1]       = pn1 - 2.f * acc[mt][1];
            distS[(r + 8) * 513 + colg]     = pn0 - 2.f * acc[mt][2];
            distS[(r + 8) * 513 + colg + 1] = pn1 - 2.f * acc[mt][3];
        }
    }
    __syncthreads();

    // per-row min: 8 threads per row, 64 entries each
    int row = tid >> 3, seg = tid & 7;
    const float* dr = distS + row * 513 + seg * 64;
    float mn = 3.4e38f;
    #pragma unroll 8
    for (int i = 0; i < 64; i++) mn = fminf(mn, dr[i]);
    #pragma unroll
    for (int o = 1; o < 8; o <<= 1) mn = fminf(mn, __shfl_xor_sync(0xffffffffu, mn, o));

    // candidate shortlist within margin
    float thr = mn + MARGIN;
    for (int i = 0; i < 64; i++) {
        if (dr[i] <= thr) {
            int slot = atomicAdd(&cntS[row], 1);
            if (slot < 8) g_cand[(size_t)(row0 + row) * 8 + slot] = seg * 64 + i;
        }
    }
    __syncthreads();
    if (tid < 64) g_cnt[row0 + tid] = cntS[tid];
}

// ---------------------------------------------------------------------------
// K2: warp-per-row exact fp32 rescore of candidates + outputs + loss
// ---------------------------------------------------------------------------
__device__ __forceinline__ float dist_exact(const float* __restrict__ protos,
                                            int idx, float4 xa, float4 xb, int lane)
{
    const float4* P4 = (const float4*)protos + (size_t)idx * 64;
    float4 pa = __ldg(P4 + lane * 2);
    float4 pb = __ldg(P4 + lane * 2 + 1);
    float s = xa.x * pa.x + xa.y * pa.y + xa.z * pa.z + xa.w * pa.w
            + xb.x * pb.x + xb.y * pb.y + xb.z * pb.z + xb.w * pb.w;
    #pragma unroll
    for (int o = 16; o; o >>= 1) s += __shfl_xor_sync(0xffffffffu, s, o);
    return g_pnorm[idx] - 2.0f * s;
}

__global__ void __launch_bounds__(256)
k_output(const float* __restrict__ x, const float* __restrict__ protos,
         float* __restrict__ out_proto, float* __restrict__ out_res,
         float* __restrict__ loss)
{
    __shared__ float blockAcc;
    const int wid = threadIdx.x >> 5, lane = threadIdx.x & 31;
    if (threadIdx.x == 0) blockAcc = 0.f;
    __syncthreads();

    const int row = blockIdx.x * 8 + wid;
    const float4* X4 = (const float4*)x + (size_t)row * 64;
    float4 xa = X4[lane * 2], xb = X4[lane * 2 + 1];

    int cnt = g_cnt[row];
    float best = 3.4e38f; int bi = 0;
    if (cnt <= 8) {
        for (int c = 0; c < cnt; c++) {
            int idx = g_cand[(size_t)row * 8 + c];
            float d = dist_exact(protos, idx, xa, xb, lane);
            if (d < best || (d == best && idx < bi)) { best = d; bi = idx; }
        }
    } else {
        for (int idx = 0; idx < P_PROTOS; idx++) {   // overflow fallback (rare)
            float d = dist_exact(protos, idx, xa, xb, lane);
            if (d < best) { best = d; bi = idx; }    // ascending: first-min tie rule
        }
    }

    const float4* P4 = (const float4*)protos + (size_t)bi * 64;
    float4 pa = __ldg(P4 + lane * 2), pb = __ldg(P4 + lane * 2 + 1);
    float4 ra = make_float4(xa.x - pa.x, xa.y - pa.y, xa.z - pa.z, xa.w - pa.w);
    float4 rb = make_float4(xb.x - pb.x, xb.y - pb.y, xb.z - pb.z, xb.w - pb.w);

    float4* OP = (float4*)out_proto + (size_t)row * 64;
    float4* OR = (float4*)out_res   + (size_t)row * 64;
    OP[lane * 2]     = pa;  OP[lane * 2 + 1] = pb;
    OR[lane * 2]     = ra;  OR[lane * 2 + 1] = rb;

    float s = ra.x * ra.x + ra.y * ra.y + ra.z * ra.z + ra.w * ra.w
            + rb.x * rb.x + rb.y * rb.y + rb.z * rb.z + rb.w * rb.w;
    #pragma unroll
    for (int o = 16; o; o >>= 1) s += __shfl_down_sync(0xffffffffu, s, o);
    if (lane == 0) atomicAdd(&blockAcc, s);
    __syncthreads();
    if (threadIdx.x == 0)
        atomicAdd(loss, blockAcc * 7.450580596923828e-08f);   // 1.25 / (T*D)
}

// ---------------------------------------------------------------------------
// launch
// ---------------------------------------------------------------------------
extern "C" void kernel_launch(void* const* d_in, const int* in_sizes, int n_in,
                              void* d_out, int out_size)
{
    const float* x      = (const float*)d_in[0];
    const float* protos = (const float*)d_in[1];
    float* out       = (float*)d_out;
    float* out_proto = out;
    float* out_res   = out + (size_t)T_ROWS * D_DIM;
    float* loss      = out + 2ull * (size_t)T_ROWS * D_DIM;

    cudaFuncSetAttribute(k_screen, cudaFuncAttributeMaxDynamicSharedMemorySize, SM_TOTAL);

    k_prep  <<<P_PROTOS, 64>>>(protos, loss);
    k_screen<<<T_ROWS / BM, 512, SM_TOTAL>>>(x);
    k_output<<<T_ROWS / 8, 256>>>(x, protos, out_proto, out_res, loss);
}